// round 5
// baseline (speedup 1.0000x reference)
#include <cuda_runtime.h>

#define NTOT   32768      // 64 graphs * 512 nodes
#define NB     64
#define NPG    512
#define LIG    128
#define GN_PER_G 1020
#define GG_PER_G 2
#define GFIX   (NB * (GN_PER_G + GG_PER_G))   // 65408
#define FULL   0xffffffffu

// d = __fsqrt_rn(d2);  d <= 8  <=>  d2 <= 64+1ulp ;  d <= 10 <=> d2 <= 100+1ulp
#define T8_BITS  0x42800001
#define T10_BITS 0x42C80001

// Scratch (device globals; zero-initialized at load; d_arrive self-resets)
__device__ unsigned d_mask_ctx[NTOT * 16];
__device__ unsigned d_mask_inter[NTOT * 16];
__device__ int d_cnt_ctx[NTOT];
__device__ int d_cnt_inter[NTOT];
__device__ int d_off_ctx[NTOT];     // within-graph exclusive row offsets
__device__ int d_off_inter[NTOT];
__device__ int d_graph_ctx[NB];
__device__ int d_graph_inter[NB];
__device__ int d_red_cnt[NB];
__device__ int d_arrive[NB];

__device__ __forceinline__ int warp_incl_scan(int x) {
    #pragma unroll
    for (int d = 1; d < 32; d <<= 1) {
        int y = __shfl_up_sync(FULL, x, d);
        if ((threadIdx.x & 31) >= d) x += y;
    }
    return x;
}

// One warp scans a 64-int array: exclusive prefix -> sh_excl[64], total -> *sh_tot.
__device__ __forceinline__ void warp_scan64_sh(const int* __restrict__ in,
                                               int* sh_excl, int* sh_tot) {
    int lane = threadIdx.x & 31;
    int v0 = in[2 * lane], v1 = in[2 * lane + 1];
    int s = v0 + v1;
    int x = warp_incl_scan(s);
    int excl = x - s;
    sh_excl[2 * lane]     = excl;
    sh_excl[2 * lane + 1] = excl + v0;
    if (lane == 31) *sh_tot = x;
}

__device__ __forceinline__ int block_excl_scan512(int v, int* sw) {
    int lane = threadIdx.x & 31, wid = threadIdx.x >> 5;
    int x = warp_incl_scan(v);
    if (lane == 31) sw[wid] = x;
    __syncthreads();
    if (wid == 0) {
        int t = (lane < 16) ? sw[lane] : 0;
        t = warp_incl_scan(t);
        if (lane < 16) sw[lane] = t;
    }
    __syncthreads();
    int add = wid ? sw[wid - 1] : 0;
    return x - v + add;
}

// ---- count + (last block per graph) scan -------------------------------
__global__ void __launch_bounds__(512) count_kernel(const float* __restrict__ X) {
    __shared__ float4 s_pos[NPG];              // xyz + class (0 glob,1 lig,2 prot)
    __shared__ int sw[16];
    __shared__ int s_last, s_red;
    int tid  = threadIdx.x, lane = tid & 31, wid = tid >> 5;
    int blk  = blockIdx.x;
    int b    = blk >> 5;
    int base = b << 9;
    int i    = blk * 16 + wid;
    int li   = i & (NPG - 1);

    {
        const float* gp = X + 3 * base;
        int t = tid;
        float cls = (t == 0 || t == LIG) ? 0.f : ((t < LIG) ? 1.f : 2.f);
        s_pos[t] = make_float4(gp[3 * t], gp[3 * t + 1], gp[3 * t + 2], cls);
    }
    __syncthreads();

    float4 a = s_pos[li];
    const float t8  = __int_as_float(T8_BITS);
    const float t10 = __int_as_float(T10_BITS);

    unsigned myc = 0u, mymi = 0u;              // lane<16 keeps its own mask word
    unsigned mbase = (unsigned)(i << 4);

    if (a.w == 2.f) {                          // protein row: ctx + inter
        #pragma unroll
        for (int k = 0; k < 16; k++) {
            float4 p = s_pos[k * 32 + lane];
            float dx = __fadd_rn(a.x, -p.x);
            float dy = __fadd_rn(a.y, -p.y);
            float dz = __fadd_rn(a.z, -p.z);
            float d2 = __fadd_rn(__fadd_rn(__fmul_rn(dx, dx), __fmul_rn(dy, dy)),
                                 __fmul_rn(dz, dz));
            bool pc = (p.w == 2.f) && (d2 <= t8);
            bool pi = (p.w == 1.f) && (d2 <= t10);
            unsigned mc = __ballot_sync(FULL, pc);
            unsigned mi = __ballot_sync(FULL, pi);
            if (lane == k) { myc = mc; mymi = mi; }
        }
        if (lane == (li >> 5)) myc &= ~(1u << (li & 31));   // remove self (d2=0)
    } else if (a.w == 1.f) {                   // ligand row: inter only, cols>=129
        #pragma unroll
        for (int k = 4; k < 16; k++) {
            float4 p = s_pos[k * 32 + lane];
            float dx = __fadd_rn(a.x, -p.x);
            float dy = __fadd_rn(a.y, -p.y);
            float dz = __fadd_rn(a.z, -p.z);
            float d2 = __fadd_rn(__fadd_rn(__fmul_rn(dx, dx), __fmul_rn(dy, dy)),
                                 __fmul_rn(dz, dz));
            bool pi = (p.w == 2.f) && (d2 <= t10);
            unsigned mi = __ballot_sync(FULL, pi);
            if (lane == k) mymi = mi;
        }
    }                                           // global row: all-zero masks

    if (lane < 16) {
        d_mask_ctx[mbase + lane]   = myc;
        d_mask_inter[mbase + lane] = mymi;
    }
    int val = (lane < 16) ? (__popc(myc) | (__popc(mymi) << 16)) : 0;
    #pragma unroll
    for (int d = 16; d; d >>= 1) val += __shfl_down_sync(FULL, val, d);
    if (lane == 0) {
        d_cnt_ctx[i]   = val & 0xffff;
        d_cnt_inter[i] = val >> 16;
    }

    // ---- last block of this graph performs the per-graph scans ----
    __syncthreads();
    if (tid == 0) {
        __threadfence();
        s_last = atomicAdd(&d_arrive[b], 1);
        s_red  = 0;
    }
    __syncthreads();
    if (s_last == 31) {
        __threadfence();
        int t = tid, row = base + t;

        int vc = d_cnt_ctx[row];
        int ec = block_excl_scan512(vc, sw);
        d_off_ctx[row] = ec;
        if (t == 511) d_graph_ctx[b] = ec + vc;
        __syncthreads();

        int vi = d_cnt_inter[row];
        int ei = block_excl_scan512(vi, sw);
        d_off_inter[row] = ei;
        if (t == 511) d_graph_inter[b] = ei + vi;

        int vr = (t >= 1 && t < LIG) ? vi : 0;  // reduced = ligand-row inter edges
        #pragma unroll
        for (int d = 16; d; d >>= 1) vr += __shfl_down_sync(FULL, vr, d);
        if (lane == 0 && vr) atomicAdd(&s_red, vr);
        __syncthreads();
        if (t == 0) {
            d_red_cnt[b] = s_red;
            d_arrive[b]  = 0;                   // reset for next graph replay
        }
    }
}

// ---- write row edges + fixed global edges + reduced arrays -------------
__global__ void __launch_bounds__(512) write_kernel(float* __restrict__ out) {
    __shared__ int sgc[NB], sgi[NB], sro[NB];
    __shared__ int stc, sti, str;
    int tid = threadIdx.x, lane = tid & 31, wid = tid >> 5;
    int blk  = blockIdx.x;
    int i    = blk * 16 + wid;
    int b    = blk >> 5;
    int s    = blk & 31;                        // slice of this graph (0..31)
    int base = b << 9;

    if (wid == 0)      warp_scan64_sh(d_graph_ctx,   sgc, &stc);
    else if (wid == 1) warp_scan64_sh(d_graph_inter, sgi, &sti);
    else if (wid == 2) warp_scan64_sh(d_red_cnt,     sro, &str);
    __syncthreads();

    int EcR = stc;
    int Ec  = EcR + GFIX;
    int Ei  = sti;
    int Er  = str;

    // row edges: lanes 0-15 ctx words, lanes 16-31 inter words
    bool lower = lane < 16;
    int w = lane & 15;
    unsigned word = lower ? d_mask_ctx[(i << 4) + w] : d_mask_inter[(i << 4) + w];
    int cnt = __popc(word);
    int I = warp_incl_scan(cnt);
    int I15 = __shfl_sync(FULL, I, 15);
    int excl = I - cnt - (lower ? 0 : I15);

    int rowoff = lower ? (sgc[b] + d_off_ctx[i]) : (sgi[b] + d_off_inter[i]);
    int pos    = lower ? (rowoff + excl) : (2 * Ec + rowoff + excl);
    int colAdd = lower ? Ec : Ei;

    float fi = (float)i;
    int cbase = base + w * 32;
    while (word) {
        int bit = __ffs(word) - 1;
        word &= word - 1;
        out[pos]          = fi;
        out[pos + colAdd] = (float)(cbase + bit);
        pos++;
    }

    // fixed global edges: this slice handles indices [32s, 32s+32)
    if (tid < 32) {
        int idx = s * 32 + tid;
        if (idx < GN_PER_G + GG_PER_G) {
            int r, c, p;
            if (idx < GN_PER_G) {
                p = EcR + b * GN_PER_G + idx;
                if (idx < 127)        { r = 0;               c = 1 + idx; }
                else if (idx < 254)   { r = idx - 126;       c = 0; }
                else if (idx < 637)   { r = 128;             c = idx - 254 + 129; }
                else                  { r = idx - 637 + 129; c = 128; }
            } else {
                int k = idx - GN_PER_G;
                p = EcR + NB * GN_PER_G + b * 2 + k;
                r = k ? 128 : 0;
                c = k ? 0   : 128;
            }
            out[p]      = (float)(base + r);
            out[Ec + p] = (float)(base + c);
        }
    }

    // reduced arrays: slice s handles k = s, s+32, s+64, ... (strided by threads)
    int rcnt = d_red_cnt[b];
    int roff = sro[b];
    int base1 = 2 * Ec + 2 * Ei + roff;
    int base2 = base1 + Er;
    float fb = (float)b, fo = (float)base;
    for (int k = s + 32 * tid; k < rcnt; k += 32 * 512) {
        out[base1 + k] = fb;
        out[base2 + k] = fo;
    }
}

extern "C" void kernel_launch(void* const* d_in, const int* in_sizes, int n_in,
                              void* d_out, int out_size) {
    const float* X = (const float*)d_in[0];
    for (int k = 0; k < n_in; k++) {
        if (in_sizes[k] == 3 * NTOT) { X = (const float*)d_in[k]; break; }
    }
    float* out = (float*)d_out;
    (void)out_size;

    count_kernel<<<NTOT / 16, 512>>>(X);
    write_kernel<<<NTOT / 16, 512>>>(out);
}

// round 6
// speedup vs baseline: 1.1485x; 1.1485x over previous
#include <cuda_runtime.h>

#define NTOT   32768      // 64 graphs * 512 nodes
#define NB     64
#define NPG    512
#define LIG    128
#define GN_PER_G 1020
#define GG_PER_G 2
#define GFIXPG (GN_PER_G + GG_PER_G)          // 1022
#define GFIX   (NB * GFIXPG)                  // 65408
#define FULL   0xffffffffu

// d = __fsqrt_rn(d2);  d <= 8  <=>  d2 <= 64+1ulp ;  d <= 10 <=> d2 <= 100+1ulp
#define T8_BITS  0x42800001
#define T10_BITS 0x42C80001

// per-word column-class masks (cols 32k..32k+31):
// ligand cols = 1..127  -> words 0..3 (word0 missing bit0)
// protein cols = 129..511 -> words 4..15 (word4 missing bit0)
#define LIGW(k)  ((k) == 0 ? 0xFFFFFFFEu : ((k) < 4 ? FULL : 0u))
#define PROTW(k) ((k) < 4 ? 0u : ((k) == 4 ? 0xFFFFFFFEu : FULL))

// Scratch (device globals; zero-initialized at load; d_arrive self-resets)
__device__ unsigned d_mask_ctx[NTOT * 16];
__device__ unsigned d_mask_inter[NTOT * 16];
__device__ int d_cnt_ctx[NTOT];
__device__ int d_cnt_inter[NTOT];
__device__ int d_off_ctx[NTOT];     // within-graph exclusive row offsets
__device__ int d_off_inter[NTOT];
__device__ int d_graph_ctx[NB];
__device__ int d_graph_inter[NB];
__device__ int d_red_cnt[NB];
__device__ int d_arrive[NB];

__device__ __forceinline__ int warp_incl_scan(int x) {
    #pragma unroll
    for (int d = 1; d < 32; d <<= 1) {
        int y = __shfl_up_sync(FULL, x, d);
        if ((threadIdx.x & 31) >= d) x += y;
    }
    return x;
}

// One warp scans a 64-int array: exclusive prefix -> sh_excl[64], total -> *sh_tot.
__device__ __forceinline__ void warp_scan64_sh(const int* __restrict__ in,
                                               int* sh_excl, int* sh_tot) {
    int lane = threadIdx.x & 31;
    int v0 = in[2 * lane], v1 = in[2 * lane + 1];
    int s = v0 + v1;
    int x = warp_incl_scan(s);
    int excl = x - s;
    sh_excl[2 * lane]     = excl;
    sh_excl[2 * lane + 1] = excl + v0;
    if (lane == 31) *sh_tot = x;
}

__device__ __forceinline__ int block_excl_scan512(int v, int* sw) {
    int lane = threadIdx.x & 31, wid = threadIdx.x >> 5;
    int x = warp_incl_scan(v);
    if (lane == 31) sw[wid] = x;
    __syncthreads();
    if (wid == 0) {
        int t = (lane < 16) ? sw[lane] : 0;
        t = warp_incl_scan(t);
        if (lane < 16) sw[lane] = t;
    }
    __syncthreads();
    int add = wid ? sw[wid - 1] : 0;
    return x - v + add;
}

// ---- count + (last block per graph) scan -------------------------------
__global__ void __launch_bounds__(512) count_kernel(const float* __restrict__ X) {
    __shared__ float4 s_pos[NPG];              // xyz + column-threshold in w
    __shared__ int sw[16];
    __shared__ int s_last, s_red;
    int tid  = threadIdx.x, lane = tid & 31, wid = tid >> 5;
    int blk  = blockIdx.x;
    int b    = blk >> 5;
    int base = b << 9;
    int i    = blk * 16 + wid;
    int li   = i & (NPG - 1);

    const float t8  = __int_as_float(T8_BITS);
    const float t10 = __int_as_float(T10_BITS);
    {
        const float* gp = X + 3 * base;
        int t = tid;
        float w = (t == 0 || t == LIG) ? -1.f : ((t < LIG) ? t10 : t8);
        s_pos[t] = make_float4(gp[3 * t], gp[3 * t + 1], gp[3 * t + 2], w);
    }
    __syncthreads();

    float4 a = s_pos[li];
    unsigned myc = 0u, mymi = 0u;              // lane<16 keeps its own mask word
    unsigned mbase = (unsigned)(i << 4);

    if (a.w == t8) {                           // protein row: ctx + inter, 1 cmp+1 ballot
        #pragma unroll
        for (int k = 0; k < 16; k++) {
            float4 p = s_pos[k * 32 + lane];
            float dx = __fadd_rn(a.x, -p.x);
            float dy = __fadd_rn(a.y, -p.y);
            float dz = __fadd_rn(a.z, -p.z);
            float d2 = __fadd_rn(__fadd_rn(__fmul_rn(dx, dx), __fmul_rn(dy, dy)),
                                 __fmul_rn(dz, dz));
            unsigned m = __ballot_sync(FULL, d2 <= p.w);
            if (lane == k) { myc = m & PROTW(k); mymi = m & LIGW(k); }
        }
        if (lane == (li >> 5)) myc &= ~(1u << (li & 31));   // remove self (d2=0)
    } else if (a.w == t10) {                   // ligand row: inter only, prot cols
        #pragma unroll
        for (int k = 4; k < 16; k++) {
            float4 p = s_pos[k * 32 + lane];
            float dx = __fadd_rn(a.x, -p.x);
            float dy = __fadd_rn(a.y, -p.y);
            float dz = __fadd_rn(a.z, -p.z);
            float d2 = __fadd_rn(__fadd_rn(__fmul_rn(dx, dx), __fmul_rn(dy, dy)),
                                 __fmul_rn(dz, dz));
            unsigned m = __ballot_sync(FULL, (p.w == t8) && (d2 <= t10));
            if (lane == k) mymi = m;
        }
    }                                           // global row: all-zero masks

    if (lane < 16) {
        d_mask_ctx[mbase + lane]   = myc;
        d_mask_inter[mbase + lane] = mymi;
    }
    int val = (lane < 16) ? (__popc(myc) | (__popc(mymi) << 16)) : 0;
    #pragma unroll
    for (int d = 16; d; d >>= 1) val += __shfl_down_sync(FULL, val, d);
    if (lane == 0) {
        d_cnt_ctx[i]   = val & 0xffff;
        d_cnt_inter[i] = val >> 16;
    }

    // ---- last arriving block of this graph performs the per-graph scans ----
    __syncthreads();
    if (tid == 0) {
        __threadfence();
        s_last = atomicAdd(&d_arrive[b], 1);
        s_red  = 0;
    }
    __syncthreads();
    if (s_last == 31) {
        __threadfence();
        int t = tid, row = base + t;

        int vc = d_cnt_ctx[row];
        int ec = block_excl_scan512(vc, sw);
        d_off_ctx[row] = ec;
        if (t == 511) d_graph_ctx[b] = ec + vc;
        __syncthreads();

        int vi = d_cnt_inter[row];
        int ei = block_excl_scan512(vi, sw);
        d_off_inter[row] = ei;
        if (t == 511) d_graph_inter[b] = ei + vi;

        int vr = (t >= 1 && t < LIG) ? vi : 0;  // reduced = ligand-row inter edges
        #pragma unroll
        for (int d = 16; d; d >>= 1) vr += __shfl_down_sync(FULL, vr, d);
        if (lane == 0 && vr) atomicAdd(&s_red, vr);
        __syncthreads();
        if (t == 0) {
            d_red_cnt[b] = s_red;
            d_arrive[b]  = 0;                   // reset for next graph replay
        }
    }
}

// ---- write: 2 rows per warp, active-word compression -------------------
// protein row (16 active words): slot 0-11 -> ctx word 4+slot, slot 12-15 -> inter word slot-12
// ligand  row (12 active words): slot 0-11 -> inter word 4+slot
__global__ void __launch_bounds__(512) write_kernel(float* __restrict__ out) {
    __shared__ int sgc[NB], sgi[NB], sro[NB];
    __shared__ int stc, sti, str;
    int tid = threadIdx.x, lane = tid & 31, wid = tid >> 5;
    int blk  = blockIdx.x;                      // 1024 blocks
    int b    = blk >> 4;
    int s    = blk & 15;                        // slice 0..15 of graph
    int base = b << 9;

    if (wid == 0)      warp_scan64_sh(d_graph_ctx,   sgc, &stc);
    else if (wid == 1) warp_scan64_sh(d_graph_inter, sgi, &sti);
    else if (wid == 2) warp_scan64_sh(d_red_cnt,     sro, &str);
    __syncthreads();

    int EcR = stc;
    int Ec  = EcR + GFIX;
    int Ei  = sti;
    int Er  = str;

    int half = lane >> 4;
    int slot = lane & 15;
    int li   = s * 32 + wid * 2 + half;         // local row within graph
    int i    = base + li;

    bool prot = li > LIG;
    bool lig  = (li >= 1) && (li < LIG);
    int wIdx  = (slot < 12) ? (4 + slot) : (slot - 12);

    unsigned word = 0u;
    bool isCtx = false;
    if (prot) {
        word  = (slot < 12) ? d_mask_ctx[(i << 4) + wIdx]
                            : d_mask_inter[(i << 4) + wIdx];
        isCtx = slot < 12;
    } else if (lig && slot < 12) {
        word = d_mask_inter[(i << 4) + wIdx];
    }

    int cnt = __popc(word);
    int I   = warp_incl_scan(cnt);
    int I11 = __shfl_sync(FULL, I, 11);
    int I15 = __shfl_sync(FULL, I, 15);
    int I27 = __shfl_sync(FULL, I, 27);
    int sub0 = half ? I15 : 0;                  // start of slot<12 subgroup
    int sub1 = half ? I27 : I11;                // start of slot>=12 subgroup
    int excl = I - cnt - ((slot < 12) ? sub0 : sub1);

    int pos, colAdd;
    if (isCtx) { pos = sgc[b] + d_off_ctx[i] + excl;          colAdd = Ec; }
    else       { pos = 2 * Ec + sgi[b] + d_off_inter[i] + excl; colAdd = Ei; }

    float fi = (float)i;
    int cbase = base + wIdx * 32;
    while (word) {
        int bit = __ffs(word) - 1;
        word &= word - 1;
        out[pos]          = fi;
        out[pos + colAdd] = (float)(cbase + bit);
        pos++;
    }

    // fixed global edges: slice s handles idx in [64s, 64s+64)
    if (tid < 64) {
        int idx = s * 64 + tid;
        if (idx < GFIXPG) {
            int r, c, p;
            if (idx < GN_PER_G) {
                p = EcR + b * GN_PER_G + idx;
                if (idx < 127)        { r = 0;               c = 1 + idx; }
                else if (idx < 254)   { r = idx - 126;       c = 0; }
                else if (idx < 637)   { r = 128;             c = idx - 254 + 129; }
                else                  { r = idx - 637 + 129; c = 128; }
            } else {
                int k = idx - GN_PER_G;
                p = EcR + NB * GN_PER_G + b * 2 + k;
                r = k ? 128 : 0;
                c = k ? 0   : 128;
            }
            out[p]      = (float)(base + r);
            out[Ec + p] = (float)(base + c);
        }
    }

    // reduced arrays: slice s handles k ≡ s (mod 16)
    int rcnt = d_red_cnt[b];
    int roff = sro[b];
    int base1 = 2 * Ec + 2 * Ei + roff;
    int base2 = base1 + Er;
    float fb = (float)b, fo = (float)base;
    for (int k = s + 16 * tid; k < rcnt; k += 16 * 512) {
        out[base1 + k] = fb;
        out[base2 + k] = fo;
    }
}

extern "C" void kernel_launch(void* const* d_in, const int* in_sizes, int n_in,
                              void* d_out, int out_size) {
    const float* X = (const float*)d_in[0];
    for (int k = 0; k < n_in; k++) {
        if (in_sizes[k] == 3 * NTOT) { X = (const float*)d_in[k]; break; }
    }
    float* out = (float*)d_out;
    (void)out_size;

    count_kernel<<<NTOT / 16, 512>>>(X);
    write_kernel<<<NTOT / 32, 512>>>(out);
}

// round 7
// speedup vs baseline: 1.3288x; 1.1570x over previous
#include <cuda_runtime.h>

#define NTOT   32768      // 64 graphs * 512 nodes
#define NB     64
#define NPG    512
#define LIG    128
#define GN_PER_G 1020
#define GG_PER_G 2
#define GFIXPG (GN_PER_G + GG_PER_G)          // 1022
#define GFIX   (NB * GFIXPG)                  // 65408
#define FULL   0xffffffffu

// d = __fsqrt_rn(d2);  d <= 8  <=>  d2 <= 64+1ulp ;  d <= 10 <=> d2 <= 100+1ulp
#define T8_BITS  0x42800001
#define T10_BITS 0x42C80001

// Scratch (device globals; zero-initialized at load; d_arrive self-resets)
__device__ unsigned d_mask_ctx[NTOT * 16];
__device__ unsigned d_mask_inter[NTOT * 16];
__device__ int d_cnt_ctx[NTOT];
__device__ int d_cnt_inter[NTOT];
__device__ int d_off_ctx[NTOT];     // within-graph exclusive row offsets
__device__ int d_off_inter[NTOT];
__device__ int d_graph_ctx[NB];
__device__ int d_graph_inter[NB];
__device__ int d_red_cnt[NB];
__device__ int d_arrive[NB];

__device__ __forceinline__ int warp_incl_scan(int x) {
    #pragma unroll
    for (int d = 1; d < 32; d <<= 1) {
        int y = __shfl_up_sync(FULL, x, d);
        if ((threadIdx.x & 31) >= d) x += y;
    }
    return x;
}

// One warp scans a 64-int array: exclusive prefix -> sh_excl[64], total -> *sh_tot.
__device__ __forceinline__ void warp_scan64_sh(const int* __restrict__ in,
                                               int* sh_excl, int* sh_tot) {
    int lane = threadIdx.x & 31;
    int v0 = in[2 * lane], v1 = in[2 * lane + 1];
    int s = v0 + v1;
    int x = warp_incl_scan(s);
    int excl = x - s;
    sh_excl[2 * lane]     = excl;
    sh_excl[2 * lane + 1] = excl + v0;
    if (lane == 31) *sh_tot = x;
}

__device__ __forceinline__ int block_excl_scan512(int v, int* sw) {
    int lane = threadIdx.x & 31, wid = threadIdx.x >> 5;
    int x = warp_incl_scan(v);
    if (lane == 31) sw[wid] = x;
    __syncthreads();
    if (wid == 0) {
        int t = (lane < 16) ? sw[lane] : 0;
        t = warp_incl_scan(t);
        if (lane < 16) sw[lane] = t;
    }
    __syncthreads();
    int add = wid ? sw[wid - 1] : 0;
    return x - v + add;
}

// ---- count: 4 rows per warp, 64 rows per block, fused per-graph scan ----
__global__ void __launch_bounds__(512) count_kernel(const float* __restrict__ X) {
    __shared__ float4 s_pos[NPG];
    __shared__ int sw[16];
    __shared__ int s_last, s_red;
    int tid  = threadIdx.x, lane = tid & 31, wid = tid >> 5;
    int blk  = blockIdx.x;                     // 512 blocks, 8 per graph
    int b    = blk >> 3;
    int base = b << 9;
    int li0  = (blk & 7) * 64 + wid * 4;       // first of this warp's 4 rows

    {
        const float* gp = X + 3 * base;
        int t = tid;
        s_pos[t] = make_float4(gp[3 * t], gp[3 * t + 1], gp[3 * t + 2], 0.f);
    }
    __syncthreads();

    const float t8  = __int_as_float(T8_BITS);
    const float t10 = __int_as_float(T10_BITS);

    float4 a0 = s_pos[li0 + 0];
    float4 a1 = s_pos[li0 + 1];
    float4 a2 = s_pos[li0 + 2];
    float4 a3 = s_pos[li0 + 3];
    float hi0 = (li0 + 0 > LIG) ? t8 : t10;    // threshold for protein cols
    float hi1 = (li0 + 1 > LIG) ? t8 : t10;
    float hi2 = (li0 + 2 > LIG) ? t8 : t10;
    float hi3 = (li0 + 3 > LIG) ? t8 : t10;

    unsigned mb0 = 0u, mb1 = 0u, mb2 = 0u, mb3 = 0u;   // lane k keeps word k

    #pragma unroll
    for (int k = 0; k < 16; k++) {
        float4 p = s_pos[k * 32 + lane];
        #define PAIR(A, HI, MB)                                                   \
        {                                                                         \
            float dx = __fadd_rn(A.x, -p.x);                                      \
            float dy = __fadd_rn(A.y, -p.y);                                      \
            float dz = __fadd_rn(A.z, -p.z);                                      \
            float d2 = __fadd_rn(__fadd_rn(__fmul_rn(dx, dx), __fmul_rn(dy, dy)), \
                                 __fmul_rn(dz, dz));                              \
            float thr = (k < 4) ? t10 : HI;                                       \
            unsigned m = __ballot_sync(FULL, d2 <= thr);                          \
            if (lane == k) MB = m;                                                \
        }
        PAIR(a0, hi0, mb0)
        PAIR(a1, hi1, mb1)
        PAIR(a2, hi2, mb2)
        PAIR(a3, hi3, mb3)
        #undef PAIR
    }

    // classification (lane < 16 holds word `lane` of each row)
    unsigned LIGWl  = (lane == 0) ? 0xFFFFFFFEu : ((lane < 4)  ? FULL : 0u);
    unsigned PROTWl = (lane < 4)  ? 0u          : ((lane == 4) ? 0xFFFFFFFEu : FULL);

    #define EMIT(R, MB)                                                          \
    {                                                                            \
        int li = li0 + R, i = base + li;                                         \
        unsigned pm = (li > LIG) ? FULL : 0u;                                    \
        unsigned lm = (li >= 1 && li < LIG) ? FULL : 0u;                         \
        unsigned myc  = MB & PROTWl & pm;                                        \
        unsigned mymi = (MB & LIGWl & pm) | (MB & PROTWl & lm);                  \
        if (pm && lane == (li >> 5)) myc &= ~(1u << (li & 31));                  \
        if (lane < 16) {                                                         \
            d_mask_ctx[(i << 4) + lane]   = myc;                                 \
            d_mask_inter[(i << 4) + lane] = mymi;                                \
        }                                                                        \
        int val = (lane < 16) ? (__popc(myc) | (__popc(mymi) << 16)) : 0;        \
        _Pragma("unroll")                                                        \
        for (int d = 16; d; d >>= 1) val += __shfl_down_sync(FULL, val, d);      \
        if (lane == 0) {                                                         \
            d_cnt_ctx[i]   = val & 0xffff;                                       \
            d_cnt_inter[i] = val >> 16;                                          \
        }                                                                        \
    }
    EMIT(0, mb0)
    EMIT(1, mb1)
    EMIT(2, mb2)
    EMIT(3, mb3)
    #undef EMIT

    // ---- last arriving block of this graph performs the per-graph scans ----
    __syncthreads();
    if (tid == 0) {
        __threadfence();
        s_last = atomicAdd(&d_arrive[b], 1);
        s_red  = 0;
    }
    __syncthreads();
    if (s_last == 7) {
        __threadfence();
        int t = tid, row = base + t;

        int vc = d_cnt_ctx[row];
        int ec = block_excl_scan512(vc, sw);
        d_off_ctx[row] = ec;
        if (t == 511) d_graph_ctx[b] = ec + vc;
        __syncthreads();

        int vi = d_cnt_inter[row];
        int ei = block_excl_scan512(vi, sw);
        d_off_inter[row] = ei;
        if (t == 511) d_graph_inter[b] = ei + vi;

        int vr = (t >= 1 && t < LIG) ? vi : 0;  // reduced = ligand-row inter edges
        #pragma unroll
        for (int d = 16; d; d >>= 1) vr += __shfl_down_sync(FULL, vr, d);
        if (lane == 0 && vr) atomicAdd(&s_red, vr);
        __syncthreads();
        if (t == 0) {
            d_red_cnt[b] = s_red;
            d_arrive[b]  = 0;                   // reset for next graph replay
        }
    }
}

// ---- write: 2 rows per warp, active-word compression -------------------
__global__ void __launch_bounds__(512) write_kernel(float* __restrict__ out) {
    __shared__ int sgc[NB], sgi[NB], sro[NB];
    __shared__ int stc, sti, str;
    int tid = threadIdx.x, lane = tid & 31, wid = tid >> 5;
    int blk  = blockIdx.x;                      // 1024 blocks
    int b    = blk >> 4;
    int s    = blk & 15;                        // slice 0..15 of graph
    int base = b << 9;

    if (wid == 0)      warp_scan64_sh(d_graph_ctx,   sgc, &stc);
    else if (wid == 1) warp_scan64_sh(d_graph_inter, sgi, &sti);
    else if (wid == 2) warp_scan64_sh(d_red_cnt,     sro, &str);
    __syncthreads();

    int EcR = stc;
    int Ec  = EcR + GFIX;
    int Ei  = sti;
    int Er  = str;

    int half = lane >> 4;
    int slot = lane & 15;
    int li   = s * 32 + wid * 2 + half;         // local row within graph
    int i    = base + li;

    bool prot = li > LIG;
    bool lig  = (li >= 1) && (li < LIG);
    int wIdx  = (slot < 12) ? (4 + slot) : (slot - 12);

    unsigned word = 0u;
    bool isCtx = false;
    if (prot) {
        word  = (slot < 12) ? d_mask_ctx[(i << 4) + wIdx]
                            : d_mask_inter[(i << 4) + wIdx];
        isCtx = slot < 12;
    } else if (lig && slot < 12) {
        word = d_mask_inter[(i << 4) + wIdx];
    }

    int cnt = __popc(word);
    int I   = warp_incl_scan(cnt);
    int I11 = __shfl_sync(FULL, I, 11);
    int I15 = __shfl_sync(FULL, I, 15);
    int I27 = __shfl_sync(FULL, I, 27);
    int sub0 = half ? I15 : 0;                  // start of slot<12 subgroup
    int sub1 = half ? I27 : I11;                // start of slot>=12 subgroup
    int excl = I - cnt - ((slot < 12) ? sub0 : sub1);

    int pos, colAdd;
    if (isCtx) { pos = sgc[b] + d_off_ctx[i] + excl;            colAdd = Ec; }
    else       { pos = 2 * Ec + sgi[b] + d_off_inter[i] + excl; colAdd = Ei; }

    float fi = (float)i;
    int cbase = base + wIdx * 32;
    while (word) {
        int bit = __ffs(word) - 1;
        word &= word - 1;
        out[pos]          = fi;
        out[pos + colAdd] = (float)(cbase + bit);
        pos++;
    }

    // fixed global edges: slice s handles idx in [64s, 64s+64)
    if (tid < 64) {
        int idx = s * 64 + tid;
        if (idx < GFIXPG) {
            int r, c, p;
            if (idx < GN_PER_G) {
                p = EcR + b * GN_PER_G + idx;
                if (idx < 127)        { r = 0;               c = 1 + idx; }
                else if (idx < 254)   { r = idx - 126;       c = 0; }
                else if (idx < 637)   { r = 128;             c = idx - 254 + 129; }
                else                  { r = idx - 637 + 129; c = 128; }
            } else {
                int k = idx - GN_PER_G;
                p = EcR + NB * GN_PER_G + b * 2 + k;
                r = k ? 128 : 0;
                c = k ? 0   : 128;
            }
            out[p]      = (float)(base + r);
            out[Ec + p] = (float)(base + c);
        }
    }

    // reduced arrays: slice s handles k ≡ s (mod 16)
    int rcnt = d_red_cnt[b];
    int roff = sro[b];
    int base1 = 2 * Ec + 2 * Ei + roff;
    int base2 = base1 + Er;
    float fb = (float)b, fo = (float)base;
    for (int k = s + 16 * tid; k < rcnt; k += 16 * 512) {
        out[base1 + k] = fb;
        out[base2 + k] = fo;
    }
}

extern "C" void kernel_launch(void* const* d_in, const int* in_sizes, int n_in,
                              void* d_out, int out_size) {
    const float* X = (const float*)d_in[0];
    for (int k = 0; k < n_in; k++) {
        if (in_sizes[k] == 3 * NTOT) { X = (const float*)d_in[k]; break; }
    }
    float* out = (float*)d_out;
    (void)out_size;

    count_kernel<<<NTOT / 64, 512>>>(X);
    write_kernel<<<NTOT / 32, 512>>>(out);
}